// round 17
// baseline (speedup 1.0000x reference)
#include <cuda_runtime.h>
#include <cuda_bf16.h>
#include <cuda_fp16.h>

#define NCLUST 256
#define NPT    128
#define NEDGE  1024
#define VS     32
#define VOXN   (VS*VS*VS)   // 32768

typedef unsigned long long ull;

__device__ __forceinline__ ull pk2(float lo, float hi) {
    ull r; asm("mov.b64 %0, {%1,%2};" : "=l"(r) : "f"(lo), "f"(hi)); return r;
}
__device__ __forceinline__ void fma2(ull& d, ull a, ull b) {
    asm("fma.rn.f32x2 %0, %1, %2, %0;" : "+l"(d) : "l"(a), "l"(b));
}
__device__ __forceinline__ float2 upk2(ull v) {
    float2 r; asm("mov.b64 {%0,%1}, %2;" : "=f"(r.x), "=f"(r.y) : "l"(v)); return r;
}
__device__ __forceinline__ unsigned smem_u32(const void* p) {
    unsigned a;
    asm("{ .reg .u64 t; cvta.to.shared.u64 t, %1; cvt.u32.u64 %0, t; }" : "=r"(a) : "l"(p));
    return a;
}

// Scratch (device globals)
__device__ float  g_cvox[NCLUST * VOXN];             // 32 MB
__device__ __align__(16) __half g_c1h[NCLUST * 4096 * 16];  // 34 MB, [c][sp][ic]
__device__ __align__(16) __half g_c2h[NEDGE * 512 * 32];    // 34 MB, [e][sp][oc]
__device__ __align__(16) float g_ovx[NCLUST * NPT * VS];    // 4 MB
__device__ __align__(16) float g_ovy[NCLUST * NPT * VS];
__device__ __align__(16) float g_ovz[NCLUST * NPT * VS];
__device__ __align__(16) float g_swt[NCLUST * NPT];
__device__ unsigned char g_lp[NCLUST * 32 * NPT];    // active-p lists per (c,j)
__device__ __align__(16) float g_lt[NCLUST * 32 * NPT];
__device__ int    g_lcnt[NCLUST * 32];
__device__ __align__(16) __half g_w2h[32 * 448];     // W2 fp16 [oc][tap*16+ic]
__device__ __align__(16) __half g_w3h[64 * 864];     // W3 fp16 [oc][tap*32+ic]
__device__ int    g_eidx_is_i64;
__device__ int    g_mask_is_u8;

// ---------------------------------------------------------------------------
// Kernel I: dtype detection (block 216) + weight transposes (blocks 0..215)
// ---------------------------------------------------------------------------
__global__ void init_kernel(const int* __restrict__ eidx_w,
                            const unsigned int* __restrict__ mask_w,
                            int E, int maskWords,
                            const float* __restrict__ W2,
                            const float* __restrict__ W3)
{
    if (blockIdx.x == 216) {
        __shared__ int oddNZ, bigW;
        if (threadIdx.x == 0) { oddNZ = 0; bigW = 0; }
        __syncthreads();
        for (int i = threadIdx.x; i < E; i += blockDim.x)
            if (eidx_w[2 * i + 1] != 0) atomicOr(&oddNZ, 1);
        for (int i = threadIdx.x; i < maskWords; i += blockDim.x)
            if (mask_w[i] > 1u) atomicOr(&bigW, 1);
        __syncthreads();
        if (threadIdx.x == 0) {
            g_eidx_is_i64 = (oddNZ == 0) ? 1 : 0;
            g_mask_is_u8  = bigW;
        }
        return;
    }
    int i = blockIdx.x * blockDim.x + threadIdx.x;
    if (i < 64 * 32 * 27) {
        int oc = i / (32 * 27), r = i % (32 * 27), ic = r / 27, tap = r % 27;
        g_w3h[oc * 864 + tap * 32 + ic] = __float2half(W3[i]);
    }
    if (i < 32 * 448) {
        int oc = i / 448, k = i % 448;
        float v = 0.0f;
        if (k < 432) {
            int tap = k >> 4, ic = k & 15;
            v = W2[(oc * 16 + ic) * 27 + tap];
        }
        g_w2h[i] = __float2half(v);
    }
}

// ---------------------------------------------------------------------------
// Kernel 0a: per-cluster reduction + overlap tables + compact (p,ty) lists
// ---------------------------------------------------------------------------
__global__ __launch_bounds__(256) void vox_tab_kernel(
    const float* __restrict__ data,
    const int* __restrict__ clusts,
    const void* __restrict__ cmask)
{
    __shared__ __align__(16) float spx[NPT], spy[NPT], spz[NPT];
    __shared__ __align__(16) float red[6 * NPT];

    const int c = blockIdx.x;
    const int t = threadIdx.x;
    const int mask_u8 = g_mask_is_u8;

    if (t < NPT) {
        int idx = clusts[c * NPT + t];
        int m;
        if (mask_u8) m = ((const unsigned char*)cmask)[c * NPT + t];
        else         m = ((const int*)cmask)[c * NPT + t];
        float x = data[idx * 5 + 0];
        float y = data[idx * 5 + 1];
        float z = data[idx * 5 + 2];
        float v = data[idx * 5 + 4];
        spx[t] = x; spy[t] = y; spz[t] = z;
        g_swt[c * NPT + t] = m ? v : 0.0f;
        red[0*NPT + t] = m ? x :  1e9f;
        red[1*NPT + t] = m ? y :  1e9f;
        red[2*NPT + t] = m ? z :  1e9f;
        red[3*NPT + t] = m ? x : -1e9f;
        red[4*NPT + t] = m ? y : -1e9f;
        red[5*NPT + t] = m ? z : -1e9f;
    }
    __syncthreads();
    for (int s = 64; s > 0; s >>= 1) {
        if (t < s) {
            red[0*NPT + t] = fminf(red[0*NPT + t], red[0*NPT + t + s]);
            red[1*NPT + t] = fminf(red[1*NPT + t], red[1*NPT + t + s]);
            red[2*NPT + t] = fminf(red[2*NPT + t], red[2*NPT + t + s]);
            red[3*NPT + t] = fmaxf(red[3*NPT + t], red[3*NPT + t + s]);
            red[4*NPT + t] = fmaxf(red[4*NPT + t], red[4*NPT + t + s]);
            red[5*NPT + t] = fmaxf(red[5*NPT + t], red[5*NPT + t + s]);
        }
        __syncthreads();
    }
    const float minx = red[0], miny = red[NPT], minz = red[2*NPT];
    const float rx = red[3*NPT] - minx;
    const float ry = red[4*NPT] - miny;
    const float rz = red[5*NPT] - minz;
    const float mr = fmaxf(rx, fmaxf(ry, rz)) + 1.0f;
    const float gs  = 1.0f / mr;
    const float rgs = mr;
    const float ns  = 1.0f / (float)VS;

    {
        int p    = t & (NPT - 1);
        int half = t >> 7;
        float vx = (spx[p] - minx - rx * 0.5f - 0.5f) * gs + 0.5f;
        float vy = (spy[p] - miny - ry * 0.5f - 0.5f) * gs + 0.5f;
        float vz = (spz[p] - minz - rz * 0.5f - 0.5f) * gs + 0.5f;
        for (int b = half * 16; b < half * 16 + 16; ++b) {
            float lo = (float)b * ns;
            float ox = fminf(vx + gs, lo + ns) - fmaxf(vx, lo);
            float oy = fminf(vy + gs, lo + ns) - fmaxf(vy, lo);
            float oz = fminf(vz + gs, lo + ns) - fmaxf(vz, lo);
            g_ovx[c * NPT * VS + p * VS + b] = fmaxf(ox, 0.0f) * rgs;
            g_ovy[c * NPT * VS + p * VS + b] = fmaxf(oy, 0.0f) * rgs;
            g_ovz[c * NPT * VS + p * VS + b] = fmaxf(oz, 0.0f) * rgs;
        }
    }
    __syncthreads();

    // build deterministic (ascending-p) active list per j
    if (t < 32) {
        const int j = t;
        const int base = (c * 32 + j) * NPT;
        int n = 0;
        for (int p = 0; p < NPT; ++p) {
            float ty = g_swt[c * NPT + p] * g_ovy[c * NPT * VS + p * VS + j];
            if (ty != 0.0f) {
                g_lp[base + n] = (unsigned char)p;
                g_lt[base + n] = ty;
                ++n;
            }
        }
        g_lcnt[c * 32 + j] = n;
    }
}

// ---------------------------------------------------------------------------
// Kernel 0b: accumulate via compact lists. grid (C, 4). smem = ovz + ovx.
// ---------------------------------------------------------------------------
#define VOXA_SMEM (2 * NPT * VS * 4)   // 32768 B

__global__ __launch_bounds__(256) void vox_acc_kernel()
{
    extern __shared__ __align__(16) float dsmv[];
    float* ovz = dsmv;
    float* ovx = dsmv + NPT * VS;

    const int c = blockIdx.x;
    const int pass = blockIdx.y;
    const int t = threadIdx.x;

    {
        const float4* sz = (const float4*)(g_ovz + c * NPT * VS);
        const float4* sx = (const float4*)(g_ovx + c * NPT * VS);
#pragma unroll
        for (int r = 0; r < 4; ++r) {
            int i = t + r * 256;
            ((float4*)ovz)[i] = sz[i];
            ((float4*)ovx)[i] = sx[i];
        }
    }
    __syncthreads();

    float* outp = g_cvox + (size_t)c * VOXN;
    {
        int jk = t + pass * 256;
        int j = jk >> 5, k = jk & 31;
        const int cnt = g_lcnt[c * 32 + j];
        const unsigned char* lp = g_lp + (c * 32 + j) * NPT;
        const float* lt = g_lt + (c * 32 + j) * NPT;
        ull acc[16];
#pragma unroll
        for (int i = 0; i < 16; ++i) acc[i] = 0ULL;
        for (int s = 0; s < cnt; ++s) {
            const int p = lp[s];
            const float ty = lt[s];
            float tz = ty * ovz[p * VS + k];
            ull tz2 = pk2(tz, tz);
            const ulonglong2* ox2 = (const ulonglong2*)&ovx[p * VS];
#pragma unroll
            for (int i4 = 0; i4 < 8; ++i4) {
                ulonglong2 o = ox2[i4];
                fma2(acc[i4 * 2],     o.x, tz2);
                fma2(acc[i4 * 2 + 1], o.y, tz2);
            }
        }
#pragma unroll
        for (int i = 0; i < 16; ++i) {
            float2 p2 = upk2(acc[i]);
            outp[(2 * i)     * 1024 + jk] = p2.x;
            outp[(2 * i + 1) * 1024 + jk] = p2.y;
        }
    }
}

// ---------------------------------------------------------------------------
// Kernel 1: per-CLUSTER linear conv1, z-slab tiling. Output fp16 [sp][ic].
// ---------------------------------------------------------------------------
#define C1SD 36
#define C1PL (33 * C1SD)     // 1188
#define C1SZ (9 * C1PL)      // 10692 floats

__global__ __launch_bounds__(256, 2) void conv1c_kernel(
    const float* __restrict__ W1)
{
    __shared__ __align__(16) float s_in[C1SZ];
    __shared__ __align__(16) float s_w[27 * 16];

    const int c    = blockIdx.x >> 2;
    const int slab = blockIdx.x & 3;
    const int t = threadIdx.x;
    const float* __restrict__ A = g_cvox + (size_t)c * VOXN;

    for (int i = t; i < C1SZ; i += 256) s_in[i] = 0.0f;
    for (int i = t; i < 432; i += 256) {
        int oc = i / 27, tap = i % 27;
        s_w[tap * 16 + oc] = W1[i];
    }
    __syncthreads();

    const int z0 = slab * 8;
#pragma unroll
    for (int r = 0; r < 9; ++r) {
        int i4 = t + r * 256;
        int zz = i4 >> 8, j = i4 & 255;
        int gz = z0 + zz;
        if (gz < 32) {
            float4 v = *(const float4*)&A[gz * 1024 + j * 4];
            *(float4*)&s_in[zz * C1PL + (j >> 3) * C1SD + (j & 7) * 4] = v;
        }
    }
    __syncthreads();

    const int x = t & 15, y = t >> 4;

    ull acc[4][8];
#pragma unroll
    for (int q = 0; q < 4; ++q)
#pragma unroll
        for (int m = 0; m < 8; ++m) acc[q][m] = 0ULL;

#pragma unroll
    for (int dz = 0; dz < 3; ++dz)
#pragma unroll
        for (int dy = 0; dy < 3; ++dy) {
            float2 v01[4];
            float  v2s[4];
#pragma unroll
            for (int q = 0; q < 4; ++q) {
                const int o = (2 * q + dz) * C1PL + (2 * y + dy) * C1SD + 2 * x;
                v01[q] = *(const float2*)&s_in[o];
                v2s[q] = s_in[o + 2];
            }
#pragma unroll
            for (int dx = 0; dx < 3; ++dx) {
                const int tap = (dz * 3 + dy) * 3 + dx;
                const ulonglong2 w01 = *(const ulonglong2*)&s_w[tap * 16];
                const ulonglong2 w23 = *(const ulonglong2*)&s_w[tap * 16 + 4];
                const ulonglong2 w45 = *(const ulonglong2*)&s_w[tap * 16 + 8];
                const ulonglong2 w67 = *(const ulonglong2*)&s_w[tap * 16 + 12];
#pragma unroll
                for (int q = 0; q < 4; ++q) {
                    float v = (dx == 0) ? v01[q].x : (dx == 1) ? v01[q].y : v2s[q];
                    ull vv = pk2(v, v);
                    fma2(acc[q][0], vv, w01.x);
                    fma2(acc[q][1], vv, w01.y);
                    fma2(acc[q][2], vv, w23.x);
                    fma2(acc[q][3], vv, w23.y);
                    fma2(acc[q][4], vv, w45.x);
                    fma2(acc[q][5], vv, w45.y);
                    fma2(acc[q][6], vv, w67.x);
                    fma2(acc[q][7], vv, w67.y);
                }
            }
        }

    __half* outp = g_c1h + (size_t)c * 65536;
#pragma unroll
    for (int q = 0; q < 4; ++q) {
        const int oz = slab * 4 + q;
        const int sp = oz * 256 + y * 16 + x;
        unsigned hv[8];
#pragma unroll
        for (int m = 0; m < 8; ++m) {
            float2 p = upk2(acc[q][m]);
            __half2 h = __floats2half2_rn(p.x, p.y);
            hv[m] = *(unsigned*)&h;
        }
        uint4* o4 = (uint4*)(outp + sp * 16);
        o4[0] = make_uint4(hv[0], hv[1], hv[2], hv[3]);
        o4[1] = make_uint4(hv[4], hv[5], hv[6], hv[7]);
    }
}

// ---------------------------------------------------------------------------
// Kernel 2: conv2 via mma.sync m16n8k16. grid = E*2.
// Fill computes relu(A+B+b1) inline from fp16 g_c1h.
// ---------------------------------------------------------------------------
#define C2_B_ROWB   912
#define C2_B_BYTES  (32 * C2_B_ROWB)           // 29184
#define C2_ACT_BYTES (5 * 17 * 18 * 48)        // 73440
#define C2MM_SMEM   (C2_B_BYTES + C2_ACT_BYTES + 256)

__global__ __launch_bounds__(256) void conv2_mma_kernel(
    const int* __restrict__ eidx,
    const float* __restrict__ b1,
    const float* __restrict__ b2,
    int E, int C)
{
    extern __shared__ __align__(16) char sm2[];
    char*  sB     = sm2;
    char*  sAct   = sm2 + C2_B_BYTES;
    float* sStage = (float*)sAct;               // ALIAS: act dead when staging
    float* sB2    = (float*)(sm2 + C2_B_BYTES + C2_ACT_BYTES);

    const int e  = blockIdx.x >> 1;
    const int hb = blockIdx.x & 1;
    const int t = threadIdx.x;
    const int w = t >> 5, lane = t & 31;

    int ca, cb;
    if (g_eidx_is_i64) { ca = eidx[2 * e]; cb = eidx[2 * (E + e)]; }
    else               { ca = eidx[e];     cb = eidx[E + e];       }
    ca = min(max(ca, 0), C - 1);
    cb = min(max(cb, 0), C - 1);

    if (t < 32) sB2[t] = b2[t];

    {
        const unsigned* w2u = (const unsigned*)g_w2h;
        for (int j = t; j < 32 * 224; j += 256) {
            int row = j / 224, ku = j % 224;
            *(unsigned*)(sB + row * C2_B_ROWB + ku * 4) = w2u[j];
        }
    }
    __syncthreads();

    const uint4* __restrict__ A4 = (const uint4*)(g_c1h + (size_t)ca * 65536);
    const uint4* __restrict__ B4 = (const uint4*)(g_c1h + (size_t)cb * 65536);

    float bf[16];
#pragma unroll
    for (int q = 0; q < 4; ++q) {
        float4 b4 = __ldg((const float4*)b1 + q);
        bf[4 * q] = b4.x; bf[4 * q + 1] = b4.y;
        bf[4 * q + 2] = b4.z; bf[4 * q + 3] = b4.w;
    }

    const int xr   = lane & 7;
    const int ysel = (lane >> 3) & 1;
    const int hh   = (lane >> 4) & 1;
    const int zloc = w & 1, ypair = w >> 1;
    const unsigned actB = smem_u32(sAct);
    const unsigned bBs  = smem_u32(sB);
    const int bgrp = lane >> 3, brow = lane & 7;
    const unsigned bAddr0 = bBs + (unsigned)(((bgrp >> 1) * 8 + brow) * C2_B_ROWB
                                             + (bgrp & 1) * 16);
    float* stage = sStage + w * (16 * 34);
    __half* outp = g_c2h + (size_t)e * 16384;

    for (int t2 = 2 * hb; t2 < 2 * hb + 2; ++t2) {
        // ---- fill: relu(A+B+b1) fp16 inline
#pragma unroll
        for (int r = 0; r < 6; ++r) {
            int i = t + r * 256;
            if (i < 1445) {
                int p = i / 289, rem = i % 289, yy = rem / 17, xx = rem % 17;
                int zz = t2 * 4 + p;
                uint4 u0 = make_uint4(0u, 0u, 0u, 0u), u1 = u0;
                if (zz < 16 && yy < 16 && xx < 16) {
                    int sp = (zz * 16 + yy) * 16 + xx;
                    unsigned ua[8], ub[8], hv[8];
                    *(uint4*)ua       = A4[sp * 2];
                    *(uint4*)(ua + 4) = A4[sp * 2 + 1];
                    *(uint4*)ub       = B4[sp * 2];
                    *(uint4*)(ub + 4) = B4[sp * 2 + 1];
#pragma unroll
                    for (int q = 0; q < 8; ++q) {
                        float2 fa = __half22float2(*(__half2*)&ua[q]);
                        float2 fb = __half22float2(*(__half2*)&ub[q]);
                        __half2 h = __floats2half2_rn(
                            fmaxf(fa.x + fb.x + bf[2 * q], 0.0f),
                            fmaxf(fa.y + fb.y + bf[2 * q + 1], 0.0f));
                        hv[q] = *(unsigned*)&h;
                    }
                    u0 = make_uint4(hv[0], hv[1], hv[2], hv[3]);
                    u1 = make_uint4(hv[4], hv[5], hv[6], hv[7]);
                }
                int voff = ((p * 17 + yy) * 18 + (xx & 1) * 9 + (xx >> 1)) * 48;
                *(uint4*)(sAct + voff)      = u0;
                *(uint4*)(sAct + voff + 16) = u1;
            }
        }
        __syncthreads();

        float acc[16];
#pragma unroll
        for (int q = 0; q < 16; ++q) acc[q] = 0.0f;

#pragma unroll
        for (int dz = 0; dz < 3; ++dz)
#pragma unroll
            for (int dy = 0; dy < 3; ++dy)
#pragma unroll
                for (int dx = 0; dx < 3; ++dx) {
                    const int g = (dz * 3 + dy) * 3 + dx;
                    unsigned bfr[8];
                    {
                        unsigned a0 = bAddr0 + (unsigned)(g * 32);
                        asm volatile(
                            "ldmatrix.sync.aligned.m8n8.x4.shared.b16 {%0,%1,%2,%3}, [%4];"
                            : "=r"(bfr[0]), "=r"(bfr[1]), "=r"(bfr[2]), "=r"(bfr[3])
                            : "r"(a0));
                        asm volatile(
                            "ldmatrix.sync.aligned.m8n8.x4.shared.b16 {%0,%1,%2,%3}, [%4];"
                            : "=r"(bfr[4]), "=r"(bfr[5]), "=r"(bfr[6]), "=r"(bfr[7])
                            : "r"(a0 + 16u * C2_B_ROWB));
                    }
                    const int p = 2 * zloc + dz;
                    const int parity = dx & 1;
                    const int xh = xr + (dx >> 1);
                    const int yv = 4 * ypair + 2 * ysel + dy;
                    unsigned aAddr = actB
                        + (unsigned)(((p * 17 + yv) * 18 + parity * 9 + xh) * 48
                                     + hh * 16);
                    unsigned af[4];
                    asm volatile(
                        "ldmatrix.sync.aligned.m8n8.x4.shared.b16 {%0,%1,%2,%3}, [%4];"
                        : "=r"(af[0]), "=r"(af[1]), "=r"(af[2]), "=r"(af[3])
                        : "r"(aAddr));
#pragma unroll
                    for (int nt = 0; nt < 4; ++nt) {
                        float* c = &acc[nt * 4];
                        asm volatile(
                            "mma.sync.aligned.m16n8k16.row.col.f32.f16.f16.f32 "
                            "{%0,%1,%2,%3}, {%4,%5,%6,%7}, {%8,%9}, {%0,%1,%2,%3};"
                            : "+f"(c[0]), "+f"(c[1]), "+f"(c[2]), "+f"(c[3])
                            : "r"(af[0]), "r"(af[1]), "r"(af[2]), "r"(af[3]),
                              "r"(bfr[nt * 2]), "r"(bfr[nt * 2 + 1]));
                    }
                }

        __syncthreads();   // act dead -> stage may overwrite

        {
            const int row = lane >> 2, col2 = (lane & 3) * 2;
#pragma unroll
            for (int nt = 0; nt < 4; ++nt) {
                const int cb0 = nt * 8 + col2;
                *(float2*)&stage[row * 34 + cb0]       =
                    make_float2(acc[nt * 4 + 0], acc[nt * 4 + 1]);
                *(float2*)&stage[(row + 8) * 34 + cb0] =
                    make_float2(acc[nt * 4 + 2], acc[nt * 4 + 3]);
            }
            __syncwarp();
            {
                const int spq = lane & 15, half = lane >> 4;
                const int z = t2 * 2 + zloc;
                const int spg = z * 64 + ypair * 16 + spq;
                unsigned hv[8];
#pragma unroll
                for (int j = 0; j < 8; ++j) {
                    float lo = fmaxf(stage[spq * 34 + half * 16 + 2 * j]
                                     + sB2[half * 16 + 2 * j], 0.0f);
                    float hi = fmaxf(stage[spq * 34 + half * 16 + 2 * j + 1]
                                     + sB2[half * 16 + 2 * j + 1], 0.0f);
                    __half2 h = __floats2half2_rn(lo, hi);
                    hv[j] = *(unsigned*)&h;
                }
                uint4* dst = (uint4*)&outp[spg * 32 + half * 16];
                dst[0] = make_uint4(hv[0], hv[1], hv[2], hv[3]);
                dst[1] = make_uint4(hv[4], hv[5], hv[6], hv[7]);
            }
        }
        __syncthreads();
    }
}

// ---------------------------------------------------------------------------
// Kernel 3: conv3 via mma.sync m16n8k16 + relu + mean-pool + FC.
// ---------------------------------------------------------------------------
#define C3_ACT_B   64800        // 9 planes x 9 y x 10 x-slots x 80B
#define C3_W_ROWB  592
#define C3_W_B     (64 * C3_W_ROWB)     // 37888
#define C3MM_SMEM  (C3_ACT_B + C3_W_B + 512)

__global__ __launch_bounds__(256) void conv3_mma_kernel(
    const float* __restrict__ b3,
    const float* __restrict__ Wfc,
    const float* __restrict__ bfc,
    float* __restrict__ out)
{
    extern __shared__ __align__(16) char sm3[];
    char*  sAct   = sm3;
    char*  sW     = sm3 + C3_ACT_B;
    float* sStage = (float*)sW;                    // alias after mma done
    float* sB3    = (float*)(sm3 + C3_ACT_B + C3_W_B);
    float* sPooled = sB3 + 64;

    const int e = blockIdx.x;
    const int t = threadIdx.x;
    const int w = t >> 5, lane = t & 31;

    if (t < 64) sB3[t] = b3[t];

    for (int i = t; i < C3_ACT_B / 4; i += 256) ((unsigned*)sAct)[i] = 0u;
    __syncthreads();
    {
        const uint4* src = (const uint4*)(g_c2h + (size_t)e * 16384);   // 2048
#pragma unroll
        for (int r = 0; r < 8; ++r) {
            int i = t + r * 256;
            int sp = i >> 2, part = i & 3;
            uint4 v = src[i];
            int x = sp & 7, y = (sp >> 3) & 7, z = sp >> 6;
            int va = z * 7200 + y * 800 + ((x & 1) * 5 + (x >> 1)) * 80 + part * 16;
            *(uint4*)(sAct + va) = v;
        }
    }

    const int mt = w & 3, nh = w >> 2;
    const int lx = lane & 3, ysub = (lane >> 2) & 1;
    const int ysel = (lane >> 3) & 1, hh = lane >> 4;
    const int ly = ysel * 2 + ysub;
    const unsigned actB = smem_u32(sAct);
    const unsigned wBs  = smem_u32(sW);
    const int bgrp = lane >> 3, brow = lane & 7;
    const unsigned bAddr0 = wBs + (unsigned)((nh * 32 + (bgrp >> 1) * 8 + brow) * C3_W_ROWB
                                             + (bgrp & 1) * 16);

    float acc[16];
#pragma unroll
    for (int q = 0; q < 16; ++q) acc[q] = 0.0f;

    const unsigned* w3u = (const unsigned*)g_w3h;   // [64][432] u32

    for (int c = 0; c < 3; ++c) {
        __syncthreads();
        for (int j = t; j < 64 * 144; j += 256) {
            int oc = j / 144, jj = j % 144;
            *(unsigned*)(sW + oc * C3_W_ROWB + jj * 4) = w3u[oc * 432 + c * 144 + jj];
        }
        __syncthreads();
#pragma unroll
        for (int gl = 0; gl < 18; ++gl) {
            const int g = c * 18 + gl;
            const int tap = g >> 1, ih = g & 1;
            const int dz = tap / 9, dyr = (tap % 9) / 3, dx = tap % 3;
            const int xp = 2 * lx + dx;
            unsigned aAddr = actB
                + (unsigned)((2 * mt + dz) * 7200 + (2 * ly + dyr) * 800
                             + ((xp & 1) * 5 + (xp >> 1)) * 80 + ih * 32 + hh * 16);
            unsigned af[4];
            asm volatile(
                "ldmatrix.sync.aligned.m8n8.x4.shared.b16 {%0,%1,%2,%3}, [%4];"
                : "=r"(af[0]), "=r"(af[1]), "=r"(af[2]), "=r"(af[3])
                : "r"(aAddr));
            unsigned bfr[8];
            {
                unsigned a0 = bAddr0 + (unsigned)(gl * 32);
                asm volatile(
                    "ldmatrix.sync.aligned.m8n8.x4.shared.b16 {%0,%1,%2,%3}, [%4];"
                    : "=r"(bfr[0]), "=r"(bfr[1]), "=r"(bfr[2]), "=r"(bfr[3])
                    : "r"(a0));
                asm volatile(
                    "ldmatrix.sync.aligned.m8n8.x4.shared.b16 {%0,%1,%2,%3}, [%4];"
                    : "=r"(bfr[4]), "=r"(bfr[5]), "=r"(bfr[6]), "=r"(bfr[7])
                    : "r"(a0 + 16u * C3_W_ROWB));
            }
#pragma unroll
            for (int nt = 0; nt < 4; ++nt) {
                float* cc = &acc[nt * 4];
                asm volatile(
                    "mma.sync.aligned.m16n8k16.row.col.f32.f16.f16.f32 "
                    "{%0,%1,%2,%3}, {%4,%5,%6,%7}, {%8,%9}, {%0,%1,%2,%3};"
                    : "+f"(cc[0]), "+f"(cc[1]), "+f"(cc[2]), "+f"(cc[3])
                    : "r"(af[0]), "r"(af[1]), "r"(af[2]), "r"(af[3]),
                      "r"(bfr[nt * 2]), "r"(bfr[nt * 2 + 1]));
            }
        }
    }
    __syncthreads();   // weights dead -> stage may overwrite

    {
        const int row = lane >> 2, col2 = (lane & 3) * 2;
#pragma unroll
        for (int nt = 0; nt < 4; ++nt) {
            const int oc0 = nh * 32 + nt * 8 + col2;
            const int sp0 = mt * 16 + row;
            sStage[sp0 * 66 + oc0]
                = fmaxf(acc[nt * 4 + 0] + sB3[oc0], 0.0f);
            sStage[sp0 * 66 + oc0 + 1]
                = fmaxf(acc[nt * 4 + 1] + sB3[oc0 + 1], 0.0f);
            sStage[(sp0 + 8) * 66 + oc0]
                = fmaxf(acc[nt * 4 + 2] + sB3[oc0], 0.0f);
            sStage[(sp0 + 8) * 66 + oc0 + 1]
                = fmaxf(acc[nt * 4 + 3] + sB3[oc0 + 1], 0.0f);
        }
    }
    __syncthreads();
    if (t < 64) {
        float s = 0.0f;
#pragma unroll 8
        for (int sp = 0; sp < 64; ++sp) s += sStage[sp * 66 + t];
        sPooled[t] = s * (1.0f / 64.0f);
    }
    __syncthreads();
    if (t < 64) {
        float r = bfc[t];
#pragma unroll 8
        for (int ic = 0; ic < 64; ++ic)
            r += sPooled[ic] * __ldg(&Wfc[ic * 64 + t]);
        out[e * 64 + t] = r;
    }
}

// ---------------------------------------------------------------------------
extern "C" void kernel_launch(void* const* d_in, const int* in_sizes, int n_in,
                              void* d_out, int out_size)
{
    const float* data   = (const float*)d_in[0];
    const int*   clusts = (const int*)d_in[1];
    const void*  cmask  = d_in[2];
    const int*   eidx   = (const int*)d_in[3];
    const float* W1     = (const float*)d_in[4];
    const float* b1     = (const float*)d_in[5];
    const float* W2     = (const float*)d_in[6];
    const float* b2     = (const float*)d_in[7];
    const float* W3     = (const float*)d_in[8];
    const float* b3     = (const float*)d_in[9];
    const float* Wfc    = (const float*)d_in[10];
    const float* bfc    = (const float*)d_in[11];
    float*       out    = (float*)d_out;

    const int C = in_sizes[1] / NPT;   // 256
    const int E = in_sizes[3] / 2;     // 1024
    const int maskWords = in_sizes[2] / 4;

    cudaFuncSetAttribute(vox_acc_kernel,
        cudaFuncAttributeMaxDynamicSharedMemorySize, VOXA_SMEM);
    cudaFuncSetAttribute(conv2_mma_kernel,
        cudaFuncAttributeMaxDynamicSharedMemorySize, C2MM_SMEM);
    cudaFuncSetAttribute(conv3_mma_kernel,
        cudaFuncAttributeMaxDynamicSharedMemorySize, C3MM_SMEM);

    init_kernel<<<217, 256>>>(eidx, (const unsigned int*)cmask, E, maskWords, W2, W3);
    vox_tab_kernel<<<C, 256>>>(data, clusts, cmask);
    vox_acc_kernel<<<dim3(C, 4), 256, VOXA_SMEM>>>();
    conv1c_kernel<<<C * 4, 256>>>(W1);
    conv2_mma_kernel<<<E * 2, 256, C2MM_SMEM>>>(eidx, b1, b2, E, C);
    conv3_mma_kernel<<<E, 256, C3MM_SMEM>>>(b3, Wfc, bfc, out);
}